// round 5
// baseline (speedup 1.0000x reference)
#include <cuda_runtime.h>
#include <mma.h>
#include <math.h>

using namespace nvcuda;

#define B_      8
#define N_      1024
#define DIM_    1024
#define HEADS_  16
#define DH_     64
#define MLP_    4096
#define M_      (B_ * N_)              /* 8192 rows */
#define FUSED_N (3 * DIM_ + MLP_)      /* 7168 */

// ---------------- scratch (static device globals; no runtime allocation) ---
__device__ float g_ss[(size_t)M_ * 2 * DIM_];        // emb@W_emb (raw)
__device__ float g_xn[(size_t)M_ * DIM_];            // modulated LN(x)
__device__ float g_fused[(size_t)M_ * FUSED_N];      // qkv | mlp_h (raw)
__device__ float g_q[(size_t)M_ * DIM_];             // [B,H,N,Dh]
__device__ float g_k[(size_t)M_ * DIM_];
__device__ float g_v[(size_t)M_ * DIM_];
__device__ float g_o[(size_t)M_ * DIM_];             // attn out, [B,N,DIM]
__device__ float g_x1[(size_t)M_ * DIM_];            // first residual

// ------------------------------------------------ WMMA 3xTF32 GEMM -------
// C_raw[M,Nc] = op(A)[M,K] @ W[K,Nc].  No bias/res here (opaque acc frags);
// consumers apply bias/residual. BM=BN=128, BK=16, 256 thr, warp tile 64x32.
#define AS_LD 20
#define WS_LD 136

template <bool SILU_A>
__global__ __launch_bounds__(256, 1)
void gemm_wmma(const float* __restrict__ A, int lda,
               const float* __restrict__ abias,   // added to A cols pre-silu (or null)
               const float* __restrict__ W, int Nc,
               float* __restrict__ C, int K)
{
    __shared__ float As[128][AS_LD];   // row-major m x k16
    __shared__ float Ws[16][WS_LD];    // row-major k16 x n128

    const int tid  = threadIdx.x;
    const int warp = tid >> 5;
    const int wm   = (warp >> 2) * 64;   // warp row offset (0 or 64)
    const int wn   = (warp & 3) * 32;    // warp col offset (0..96)

    // global-load coordinates
    const int ar = tid >> 2;              // A row (two 64-row iters)
    const int ac = (tid & 3) * 4;         // A col
    const int wr = tid >> 5;              // W row (two 8-row iters)
    const int wc = (tid & 31) * 4;        // W col

    const float* Ap = A + (size_t)(blockIdx.y * 128) * lda;
    const float* Wp = W + (size_t)blockIdx.x * 128;

    wmma::fragment<wmma::accumulator, 16, 16, 8, float> acc[4][2];
#pragma unroll
    for (int i = 0; i < 4; i++)
#pragma unroll
        for (int j = 0; j < 2; j++) wmma::fill_fragment(acc[i][j], 0.f);

    float4 aReg[2], wReg[2];
#pragma unroll
    for (int i = 0; i < 2; i++) {
        aReg[i] = *(const float4*)(Ap + (size_t)(ar + i * 64) * lda + ac);
        wReg[i] = *(const float4*)(Wp + (size_t)(wr + i * 8) * Nc + wc);
    }

#pragma unroll 1
    for (int k0 = 0; k0 < K; k0 += 16) {
        // ---- stage to smem ----
#pragma unroll
        for (int i = 0; i < 2; i++) {
            float4 v = aReg[i];
            if (SILU_A) {
                v.x += abias[k0 + ac + 0];
                v.y += abias[k0 + ac + 1];
                v.z += abias[k0 + ac + 2];
                v.w += abias[k0 + ac + 3];
                v.x = v.x / (1.f + __expf(-v.x));
                v.y = v.y / (1.f + __expf(-v.y));
                v.z = v.z / (1.f + __expf(-v.z));
                v.w = v.w / (1.f + __expf(-v.w));
            }
            *(float4*)(&As[ar + i * 64][ac]) = v;
            *(float4*)(&Ws[wr + i * 8][wc]) = wReg[i];
        }
        __syncthreads();

        // ---- prefetch next tile ----
        if (k0 + 16 < K) {
#pragma unroll
            for (int i = 0; i < 2; i++) {
                aReg[i] = *(const float4*)(Ap + (size_t)(ar + i * 64) * lda + (k0 + 16) + ac);
                wReg[i] = *(const float4*)(Wp + (size_t)(k0 + 16 + wr + i * 8) * Nc + wc);
            }
        }

        // ---- compute: two k8 slices, 3xTF32 ----
#pragma unroll
        for (int ks = 0; ks < 2; ks++) {
            const int kb = ks * 8;

            wmma::fragment<wmma::matrix_b, 16, 16, 8, wmma::precision::tf32, wmma::row_major> bh[2], bl[2];
#pragma unroll
            for (int nt = 0; nt < 2; nt++) {
                wmma::load_matrix_sync(bh[nt], &Ws[kb][wn + nt * 16], WS_LD);
#pragma unroll
                for (int e = 0; e < bh[nt].num_elements; e++) {
                    float v = bh[nt].x[e];
                    float h = wmma::__float_to_tf32(v);
                    bh[nt].x[e] = h;
                    bl[nt].x[e] = wmma::__float_to_tf32(v - h);
                }
            }

#pragma unroll
            for (int mt = 0; mt < 4; mt++) {
                wmma::fragment<wmma::matrix_a, 16, 16, 8, wmma::precision::tf32, wmma::row_major> ah, al;
                wmma::load_matrix_sync(ah, &As[wm + mt * 16][kb], AS_LD);
#pragma unroll
                for (int e = 0; e < ah.num_elements; e++) {
                    float v = ah.x[e];
                    float h = wmma::__float_to_tf32(v);
                    ah.x[e] = h;
                    al.x[e] = wmma::__float_to_tf32(v - h);
                }
#pragma unroll
                for (int nt = 0; nt < 2; nt++) {
                    wmma::mma_sync(acc[mt][nt], ah, bh[nt], acc[mt][nt]);
                    wmma::mma_sync(acc[mt][nt], ah, bl[nt], acc[mt][nt]);
                    wmma::mma_sync(acc[mt][nt], al, bh[nt], acc[mt][nt]);
                }
            }
        }
        __syncthreads();
    }

    // ---- epilogue: raw store ----
    const int row0 = blockIdx.y * 128 + wm;
    const int col0 = blockIdx.x * 128 + wn;
#pragma unroll
    for (int mt = 0; mt < 4; mt++)
#pragma unroll
        for (int nt = 0; nt < 2; nt++)
            wmma::store_matrix_sync(C + (size_t)(row0 + mt * 16) * Nc + col0 + nt * 16,
                                    acc[mt][nt], Nc, wmma::mem_row_major);
}

// ------------------- elementwise: C = C + res + bias(broadcast) ----------
__global__ __launch_bounds__(256)
void add_res_bias(float* __restrict__ C, const float* __restrict__ res,
                  const float* __restrict__ bias, int Nc)
{
    const size_t i4 = (size_t)blockIdx.x * 256 + threadIdx.x;   // float4 index
    const size_t base = i4 * 4;
    const int c = (int)(base % Nc);
    float4 v = *(float4*)(C + base);
    float4 r = *(const float4*)(res + base);
    v.x += r.x + bias[c + 0];
    v.y += r.y + bias[c + 1];
    v.z += r.z + bias[c + 2];
    v.w += r.w + bias[c + 3];
    *(float4*)(C + base) = v;
}

// --------------------------- LN(x) * (1+scale) + shift  (AdaLN modulate) ---
// scale/shift come from raw g_ss + b_emb.
__global__ __launch_bounds__(256)
void ln_mod_kernel(const float* __restrict__ x,
                   const float* __restrict__ g,
                   const float* __restrict__ b,
                   const float* __restrict__ be)
{
    const int row = blockIdx.x;
    const int tid = threadIdx.x;
    const float* xr  = x + (size_t)row * DIM_;
    const float* ssr = g_ss + (size_t)row * (2 * DIM_);

    float v[4];
    float s = 0.f, sq = 0.f;
#pragma unroll
    for (int i = 0; i < 4; i++) {
        v[i] = xr[tid + i * 256];
        s += v[i];
        sq += v[i] * v[i];
    }
    __shared__ float sh[2][8];
#pragma unroll
    for (int o = 16; o; o >>= 1) {
        s  += __shfl_xor_sync(0xffffffffu, s, o);
        sq += __shfl_xor_sync(0xffffffffu, sq, o);
    }
    if ((tid & 31) == 0) { sh[0][tid >> 5] = s; sh[1][tid >> 5] = sq; }
    __syncthreads();
    if (tid < 32) {
        s  = (tid < 8) ? sh[0][tid] : 0.f;
        sq = (tid < 8) ? sh[1][tid] : 0.f;
#pragma unroll
        for (int o = 4; o; o >>= 1) {
            s  += __shfl_xor_sync(0xffffffffu, s, o);
            sq += __shfl_xor_sync(0xffffffffu, sq, o);
        }
        if (tid == 0) { sh[0][0] = s; sh[1][0] = sq; }
    }
    __syncthreads();
    s = sh[0][0]; sq = sh[1][0];

    const float mean = s * (1.f / DIM_);
    const float var  = sq * (1.f / DIM_) - mean * mean;
    const float rs   = rsqrtf(var + 1e-5f);
#pragma unroll
    for (int i = 0; i < 4; i++) {
        const int idx = tid + i * 256;
        const float scale = ssr[idx] + be[idx];
        const float shift = ssr[DIM_ + idx] + be[DIM_ + idx];
        const float xv = (v[i] - mean) * rs * g[idx] + b[idx];
        g_xn[(size_t)row * DIM_ + idx] = xv * (1.f + scale) + shift;
    }
}

// ------------- per-head q/k layernorm + transpose qkv to [B,H,N,Dh] -------
// reads raw g_fused, applies b_fused.
__global__ __launch_bounds__(256)
void qkv_norm_kernel(const float* __restrict__ qg, const float* __restrict__ qb,
                     const float* __restrict__ kg, const float* __restrict__ kb,
                     const float* __restrict__ bf)
{
    const int row = blockIdx.x;          // b*N + n
    const int bb_ = row >> 10;
    const int n   = row & 1023;
    const int tid = threadIdx.x;
    const float* fr = g_fused + (size_t)row * FUSED_N;

    // v: transpose copy (+ bias)
    for (int i = tid; i < DIM_; i += 256) {
        const int h = i >> 6, d = i & 63;
        g_v[(((size_t)(bb_ * HEADS_ + h)) * N_ + n) * DH_ + d] =
            fr[2 * DIM_ + i] + bf[2 * DIM_ + i];
    }

    const int warp = tid >> 5, lane = tid & 31;
    for (int t = warp; t < 32; t += 8) {
        const int which = t >> 4;        // 0 = q, 1 = k
        const int h = t & 15;
        const int off = which * DIM_ + h * DH_;
        const float* base = fr + off;
        float e0 = base[lane]      + bf[off + lane];
        float e1 = base[lane + 32] + bf[off + lane + 32];
        float s = e0 + e1, sq = e0 * e0 + e1 * e1;
#pragma unroll
        for (int o = 16; o; o >>= 1) {
            s  += __shfl_xor_sync(0xffffffffu, s, o);
            sq += __shfl_xor_sync(0xffffffffu, sq, o);
        }
        const float mean = s * (1.f / 64.f);
        const float var  = sq * (1.f / 64.f) - mean * mean;
        const float rs   = rsqrtf(var + 1e-5f);
        const float* gg = which ? kg : qg;
        const float* bv = which ? kb : qb;
        float* out = (which ? g_k : g_q) + (((size_t)(bb_ * HEADS_ + h)) * N_ + n) * DH_;
        out[lane]      = (e0 - mean) * rs * gg[lane]      + bv[lane];
        out[lane + 32] = (e1 - mean) * rs * gg[lane + 32] + bv[lane + 32];
    }
}

// ----------------------- flash attention: 1 query row / thread ------------
__global__ __launch_bounds__(128)
void attn_kernel()
{
    const int bh = blockIdx.y;                     // b*16 + h
    const int m  = blockIdx.x * 128 + threadIdx.x; // query index

    const float* qp = g_q + ((size_t)bh * N_ + m) * DH_;
    float q[64];
#pragma unroll
    for (int d = 0; d < 64; d++) q[d] = qp[d] * 0.125f;   // 1/sqrt(64)

    float o[64];
#pragma unroll
    for (int d = 0; d < 64; d++) o[d] = 0.f;
    float mi = -1e30f, li = 0.f;

    __shared__ float ks[64][64];
    __shared__ float vs[64][64];

    for (int t = 0; t < N_; t += 64) {
        const float4* kb = (const float4*)(g_k + ((size_t)bh * N_ + t) * DH_);
        const float4* vb = (const float4*)(g_v + ((size_t)bh * N_ + t) * DH_);
        __syncthreads();
#pragma unroll
        for (int i = 0; i < 8; i++) {
            const int idx = threadIdx.x + i * 128;
            ((float4*)ks)[idx] = kb[idx];
            ((float4*)vs)[idx] = vb[idx];
        }
        __syncthreads();

#pragma unroll 1
        for (int j = 0; j < 64; j++) {
            float s = 0.f;
#pragma unroll
            for (int d = 0; d < 64; d++) s += q[d] * ks[j][d];
            const float mn = fmaxf(mi, s);
            const float p  = __expf(s - mn);
            if (mn != mi) {
                const float corr = __expf(mi - mn);
                li *= corr;
#pragma unroll
                for (int d = 0; d < 64; d++) o[d] *= corr;
                mi = mn;
            }
            li += p;
#pragma unroll
            for (int d = 0; d < 64; d++) o[d] += p * vs[j][d];
        }
    }

    const int b = bh >> 4, h = bh & 15;
    const float inv = 1.f / li;
    float* op = g_o + ((size_t)(b * N_ + m)) * DIM_ + h * DH_;
#pragma unroll
    for (int d = 0; d < 64; d++) op[d] = o[d] * inv;
}

// --------------------------------------------------------------------------
extern "C" void kernel_launch(void* const* d_in, const int* in_sizes, int n_in,
                              void* d_out, int out_size)
{
    const float* x       = (const float*)d_in[0];
    const float* emb     = (const float*)d_in[1];
    const float* W_emb   = (const float*)d_in[2];
    const float* b_emb   = (const float*)d_in[3];
    const float* ln_g    = (const float*)d_in[4];
    const float* ln_b    = (const float*)d_in[5];
    const float* W_fused = (const float*)d_in[6];
    const float* b_fused = (const float*)d_in[7];
    const float* qn_g    = (const float*)d_in[8];
    const float* qn_b    = (const float*)d_in[9];
    const float* kn_g    = (const float*)d_in[10];
    const float* kn_b    = (const float*)d_in[11];
    const float* W_ao    = (const float*)d_in[12];
    const float* b_ao    = (const float*)d_in[13];
    const float* W_mlp   = (const float*)d_in[14];
    const float* b_mlp   = (const float*)d_in[15];
    float* out = (float*)d_out;

    float *ss, *xn, *fused, *o, *x1;
    cudaGetSymbolAddress((void**)&ss,    g_ss);
    cudaGetSymbolAddress((void**)&xn,    g_xn);
    cudaGetSymbolAddress((void**)&fused, g_fused);
    cudaGetSymbolAddress((void**)&o,     g_o);
    cudaGetSymbolAddress((void**)&x1,    g_x1);

    // 1. ss_raw = emb @ W_emb                     [8192, 2048]
    gemm_wmma<false><<<dim3(2048 / 128, M_ / 128), 256>>>(
        emb, DIM_, nullptr, W_emb, 2 * DIM_, ss, DIM_);
    // 2. xn = LN(x)*(1+scale)+shift    (b_emb folded in)
    ln_mod_kernel<<<M_, 256>>>(x, ln_g, ln_b, b_emb);
    // 3. fused_raw = xn @ W_fused                 [8192, 7168]
    gemm_wmma<false><<<dim3(FUSED_N / 128, M_ / 128), 256>>>(
        xn, DIM_, nullptr, W_fused, FUSED_N, fused, DIM_);
    // 4. per-head q/k layernorm + transpose (b_fused folded in)
    qkv_norm_kernel<<<M_, 256>>>(qn_g, qn_b, kn_g, kn_b, b_fused);
    // 5. attention
    attn_kernel<<<dim3(N_ / 128, B_ * HEADS_), 128>>>();
    // 6. x1 = x + o @ W_ao + b_ao
    gemm_wmma<false><<<dim3(DIM_ / 128, M_ / 128), 256>>>(
        o, DIM_, nullptr, W_ao, DIM_, x1, DIM_);
    add_res_bias<<<(unsigned)((size_t)M_ * DIM_ / 4 / 256), 256>>>(x1, x, b_ao, DIM_);
    // 7. out = x1 + silu(mlp_h + b_fused[3D:]) @ W_mlp + b_mlp
    gemm_wmma<true><<<dim3(DIM_ / 128, M_ / 128), 256>>>(
        fused + 3 * DIM_, FUSED_N, b_fused + 3 * DIM_, W_mlp, DIM_, out, MLP_);
    add_res_bias<<<(unsigned)((size_t)M_ * DIM_ / 4 / 256), 256>>>(out, x1, b_mlp, DIM_);
}